// round 3
// baseline (speedup 1.0000x reference)
#include <cuda_runtime.h>

// ---------------------------------------------------------------------------
// WeightedMSELoss: loss = sum(w(t) * (p - t)^2) / sum(weights)
// w(t) = weights[i] for edge[i] < t <= edge[i+1]; 0 outside (edge[0], edge[5]].
// Inputs (metadata order): predicted[N] f32, target[N] f32, weights[5] f32, edge[6] f32
// Output: scalar f32.
// HBM-bound streaming reduction: 2*N*4 B read (~256 MiB), one float out.
// ---------------------------------------------------------------------------

#define NBLOCKS  1184      // 148 SMs * 8 CTAs
#define NTHREADS 256

__device__ float g_partials[NBLOCKS];

__device__ __forceinline__ float elem_loss(float p, float t,
                                           float e0, float e1, float e2, float e3,
                                           float e4, float e5,
                                           float w0, float w1, float w2, float w3, float w4) {
    // Straight-line select chain -> FSEL, no branches.
    float w = w4;
    w = (t <= e4) ? w3 : w;
    w = (t <= e3) ? w2 : w;
    w = (t <= e2) ? w1 : w;
    w = (t <= e1) ? w0 : w;
    w = (t <= e0) ? 0.0f : w;
    w = (t >  e5) ? 0.0f : w;
    float d = p - t;
    return w * d * d;
}

__global__ void __launch_bounds__(NTHREADS)
wmse_partial_kernel(const float4* __restrict__ pred4,
                    const float4* __restrict__ targ4,
                    const float*  __restrict__ pred,
                    const float*  __restrict__ targ,
                    const float*  __restrict__ weights,
                    const float*  __restrict__ edge,
                    int n4, int n) {
    // Uniform scalars: read-only path, hoisted before the streaming loop.
    const float e0 = __ldg(&edge[0]), e1 = __ldg(&edge[1]), e2 = __ldg(&edge[2]),
                e3 = __ldg(&edge[3]), e4 = __ldg(&edge[4]), e5 = __ldg(&edge[5]);
    const float w0 = __ldg(&weights[0]), w1 = __ldg(&weights[1]),
                w2 = __ldg(&weights[2]), w3 = __ldg(&weights[3]),
                w4 = __ldg(&weights[4]);

    float acc0 = 0.0f, acc1 = 0.0f;
    const int tid_global = blockIdx.x * blockDim.x + threadIdx.x;
    const int stride = gridDim.x * blockDim.x;

    // Main loop: 2x float4 per iteration, loads front-batched for MLP.
    int i = tid_global;
    for (; i + stride < n4; i += 2 * stride) {
        float4 pa = pred4[i];
        float4 ta = targ4[i];
        float4 pb = pred4[i + stride];
        float4 tb = targ4[i + stride];
        acc0 += elem_loss(pa.x, ta.x, e0,e1,e2,e3,e4,e5, w0,w1,w2,w3,w4);
        acc0 += elem_loss(pa.y, ta.y, e0,e1,e2,e3,e4,e5, w0,w1,w2,w3,w4);
        acc0 += elem_loss(pa.z, ta.z, e0,e1,e2,e3,e4,e5, w0,w1,w2,w3,w4);
        acc0 += elem_loss(pa.w, ta.w, e0,e1,e2,e3,e4,e5, w0,w1,w2,w3,w4);
        acc1 += elem_loss(pb.x, tb.x, e0,e1,e2,e3,e4,e5, w0,w1,w2,w3,w4);
        acc1 += elem_loss(pb.y, tb.y, e0,e1,e2,e3,e4,e5, w0,w1,w2,w3,w4);
        acc1 += elem_loss(pb.z, tb.z, e0,e1,e2,e3,e4,e5, w0,w1,w2,w3,w4);
        acc1 += elem_loss(pb.w, tb.w, e0,e1,e2,e3,e4,e5, w0,w1,w2,w3,w4);
    }
    // Remainder float4s
    for (; i < n4; i += stride) {
        float4 p = pred4[i];
        float4 t = targ4[i];
        acc0 += elem_loss(p.x, t.x, e0,e1,e2,e3,e4,e5, w0,w1,w2,w3,w4);
        acc0 += elem_loss(p.y, t.y, e0,e1,e2,e3,e4,e5, w0,w1,w2,w3,w4);
        acc0 += elem_loss(p.z, t.z, e0,e1,e2,e3,e4,e5, w0,w1,w2,w3,w4);
        acc0 += elem_loss(p.w, t.w, e0,e1,e2,e3,e4,e5, w0,w1,w2,w3,w4);
    }
    // Scalar tail (N not a multiple of 4)
    int tail_idx = n4 * 4 + tid_global;
    if (tail_idx < n) {
        acc0 += elem_loss(pred[tail_idx], targ[tail_idx],
                          e0,e1,e2,e3,e4,e5, w0,w1,w2,w3,w4);
    }

    float acc = acc0 + acc1;

    // Deterministic block tree reduction
    __shared__ float sdata[NTHREADS];
    int tid = threadIdx.x;
    sdata[tid] = acc;
    __syncthreads();
    #pragma unroll
    for (int s = NTHREADS / 2; s > 32; s >>= 1) {
        if (tid < s) sdata[tid] += sdata[tid + s];
        __syncthreads();
    }
    if (tid < 32) {
        float v = sdata[tid] + sdata[tid + 32];
        #pragma unroll
        for (int off = 16; off > 0; off >>= 1)
            v += __shfl_down_sync(0xFFFFFFFFu, v, off);
        if (tid == 0) g_partials[blockIdx.x] = v;
    }
}

__global__ void __launch_bounds__(1024)
wmse_finalize_kernel(const float* __restrict__ weights, float* __restrict__ out) {
    __shared__ float sdata[1024];
    int tid = threadIdx.x;
    float v = 0.0f;
    for (int i = tid; i < NBLOCKS; i += 1024) v += g_partials[i];
    sdata[tid] = v;
    __syncthreads();
    #pragma unroll
    for (int s = 512; s > 32; s >>= 1) {
        if (tid < s) sdata[tid] += sdata[tid + s];
        __syncthreads();
    }
    if (tid < 32) {
        float x = sdata[tid] + sdata[tid + 32];
        #pragma unroll
        for (int off = 16; off > 0; off >>= 1)
            x += __shfl_down_sync(0xFFFFFFFFu, x, off);
        if (tid == 0) {
            float wsum = __ldg(&weights[0]) + __ldg(&weights[1]) + __ldg(&weights[2])
                       + __ldg(&weights[3]) + __ldg(&weights[4]);
            out[0] = x / wsum;
        }
    }
}

extern "C" void kernel_launch(void* const* d_in, const int* in_sizes, int n_in,
                              void* d_out, int out_size) {
    const float* pred    = (const float*)d_in[0];
    const float* targ    = (const float*)d_in[1];
    const float* weights = (const float*)d_in[2];
    const float* edge    = (const float*)d_in[3];
    float* out = (float*)d_out;

    int n  = in_sizes[0];
    int n4 = n / 4;

    wmse_partial_kernel<<<NBLOCKS, NTHREADS>>>(
        (const float4*)pred, (const float4*)targ, pred, targ, weights, edge, n4, n);
    wmse_finalize_kernel<<<1, 1024>>>(weights, out);
}